// round 1
// baseline (speedup 1.0000x reference)
#include <cuda_runtime.h>
#include <cuda_bf16.h>

// ---------------- device scratch (no allocations allowed) ----------------
#define MAXN 100000
#define HID 256

__device__ float g_h[MAXN * HID];        // current hidden state (also "prev")
__device__ float g_qkv[MAXN * 768];      // [n][0:256)=q, [256:512)=k, [512:768)=v
__device__ float g_attn[MAXN * HID];     // GEMM scratch (pre-LN / q@kvs)
__device__ float g_kvs[HID * HID];       // k^T v (raw, unnormalized)
__device__ float g_red[272];             // [0:256) ks_sum, [256]=sum q^2, [257]=sum k^2
__device__ float g_W[HID * 768];         // concatenated Wq|Wk|Wv
__device__ float g_b[768];               // concatenated biases

// ---------------- helpers ----------------
__device__ __forceinline__ float block_sum_256(float v, float* sm) {
    #pragma unroll
    for (int o = 16; o > 0; o >>= 1) v += __shfl_xor_sync(0xffffffffu, v, o);
    int w = threadIdx.x >> 5;
    if ((threadIdx.x & 31) == 0) sm[w] = v;
    __syncthreads();
    if (w == 0) {
        float t = (threadIdx.x < 8) ? sm[threadIdx.x] : 0.f;
        #pragma unroll
        for (int o = 4; o > 0; o >>= 1) t += __shfl_xor_sync(0xffffffffu, t, o);
        if (threadIdx.x == 0) sm[0] = t;
    }
    __syncthreads();
    float r = sm[0];
    __syncthreads();
    return r;
}

// ---------------- generic SGEMM: C[M,N] = A[M,K]@B[K,N] (+bias) ----------------
// BM=128, BN=128, BK=16, 256 threads, 8x8 per thread. N multiple of 128, K multiple of 16.
__global__ void __launch_bounds__(256) sgemm_k(
    const float* __restrict__ A, int lda,
    const float* __restrict__ B, int ldb,
    const float* __restrict__ bias,
    float* __restrict__ C, int ldc,
    int M, int K)
{
    __shared__ float As[16][128];
    __shared__ float Bs[16][128];
    const int tid = threadIdx.x;
    const int row0 = blockIdx.y * 128;
    const int col0 = blockIdx.x * 128;
    const int tx = tid & 15;
    const int ty = tid >> 4;

    float acc[8][8];
    #pragma unroll
    for (int i = 0; i < 8; i++)
        #pragma unroll
        for (int j = 0; j < 8; j++) acc[i][j] = 0.f;

    const int aRow0 = tid >> 2;          // 0..63
    const int aK0   = (tid & 3) * 4;     // 0,4,8,12
    const int bRow0 = tid >> 5;          // 0..7
    const int bCol0 = (tid & 31) * 4;    // 0..124

    for (int k0 = 0; k0 < K; k0 += 16) {
        #pragma unroll
        for (int s = 0; s < 2; s++) {
            int arow = aRow0 + s * 64;
            float4 av = make_float4(0.f, 0.f, 0.f, 0.f);
            int gr = row0 + arow;
            if (gr < M) av = *reinterpret_cast<const float4*>(&A[(long)gr * lda + k0 + aK0]);
            As[aK0 + 0][arow] = av.x;
            As[aK0 + 1][arow] = av.y;
            As[aK0 + 2][arow] = av.z;
            As[aK0 + 3][arow] = av.w;
        }
        #pragma unroll
        for (int s = 0; s < 2; s++) {
            int brow = bRow0 + s * 8;
            float4 bv = *reinterpret_cast<const float4*>(&B[(long)(k0 + brow) * ldb + col0 + bCol0]);
            *reinterpret_cast<float4*>(&Bs[brow][bCol0]) = bv;
        }
        __syncthreads();
        #pragma unroll
        for (int kk = 0; kk < 16; kk++) {
            float a[8], b[8];
            *reinterpret_cast<float4*>(a)     = *reinterpret_cast<const float4*>(&As[kk][ty * 8]);
            *reinterpret_cast<float4*>(a + 4) = *reinterpret_cast<const float4*>(&As[kk][ty * 8 + 4]);
            *reinterpret_cast<float4*>(b)     = *reinterpret_cast<const float4*>(&Bs[kk][tx * 8]);
            *reinterpret_cast<float4*>(b + 4) = *reinterpret_cast<const float4*>(&Bs[kk][tx * 8 + 4]);
            #pragma unroll
            for (int i = 0; i < 8; i++)
                #pragma unroll
                for (int j = 0; j < 8; j++)
                    acc[i][j] += a[i] * b[j];
        }
        __syncthreads();
    }

    #pragma unroll
    for (int i = 0; i < 8; i++) {
        int gr = row0 + ty * 8 + i;
        if (gr >= M) continue;
        #pragma unroll
        for (int j = 0; j < 8; j += 4) {
            int gc = col0 + tx * 8 + j;
            float4 o;
            o.x = acc[i][j + 0]; o.y = acc[i][j + 1]; o.z = acc[i][j + 2]; o.w = acc[i][j + 3];
            if (bias) {
                o.x += bias[gc]; o.y += bias[gc + 1]; o.z += bias[gc + 2]; o.w += bias[gc + 3];
            }
            *reinterpret_cast<float4*>(&C[(long)gr * ldc + gc]) = o;
        }
    }
}

// ---------------- kvs = k^T v, split-K over rows, atomic accumulate ----------------
__global__ void __launch_bounds__(256) kvs_kernel(
    const float* __restrict__ qkv, float* __restrict__ kvs, int M, int chunk)
{
    __shared__ float Ks[32][64];
    __shared__ float Vs[32][64];
    const int tile = blockIdx.x;          // 0..15
    const int m0 = (tile >> 2) * 64;
    const int d0 = (tile & 3) * 64;
    const int n0 = blockIdx.y * chunk;
    const int n1 = min(n0 + chunk, M);
    const int tid = threadIdx.x;
    const int tx = tid & 15, ty = tid >> 4;
    const int lr = tid >> 4;
    const int lc = (tid & 15) * 4;

    float acc[4][4];
    #pragma unroll
    for (int i = 0; i < 4; i++)
        #pragma unroll
        for (int j = 0; j < 4; j++) acc[i][j] = 0.f;

    for (int nb = n0; nb < n1; nb += 32) {
        #pragma unroll
        for (int s = 0; s < 2; s++) {
            int r = lr + s * 16;
            int gn = nb + r;
            float4 kv = make_float4(0.f, 0.f, 0.f, 0.f);
            float4 vv = make_float4(0.f, 0.f, 0.f, 0.f);
            if (gn < n1) {
                kv = *reinterpret_cast<const float4*>(&qkv[(long)gn * 768 + 256 + m0 + lc]);
                vv = *reinterpret_cast<const float4*>(&qkv[(long)gn * 768 + 512 + d0 + lc]);
            }
            *reinterpret_cast<float4*>(&Ks[r][lc]) = kv;
            *reinterpret_cast<float4*>(&Vs[r][lc]) = vv;
        }
        __syncthreads();
        #pragma unroll
        for (int kk = 0; kk < 32; kk++) {
            float a[4], b[4];
            *reinterpret_cast<float4*>(a) = *reinterpret_cast<const float4*>(&Ks[kk][ty * 4]);
            *reinterpret_cast<float4*>(b) = *reinterpret_cast<const float4*>(&Vs[kk][tx * 4]);
            #pragma unroll
            for (int i = 0; i < 4; i++)
                #pragma unroll
                for (int j = 0; j < 4; j++)
                    acc[i][j] += a[i] * b[j];
        }
        __syncthreads();
    }
    #pragma unroll
    for (int i = 0; i < 4; i++)
        #pragma unroll
        for (int j = 0; j < 4; j++)
            atomicAdd(&kvs[(m0 + ty * 4 + i) * 256 + d0 + tx * 4 + j], acc[i][j]);
}

// ---------------- reductions: ks_sum, sum(q^2), sum(k^2) ----------------
__global__ void __launch_bounds__(256) reduce_qk(
    const float* __restrict__ qkv, float* __restrict__ red, int M)
{
    __shared__ float sm[8];
    const int j = threadIdx.x;
    float aks = 0.f, aq2 = 0.f, ak2 = 0.f;
    for (int r = blockIdx.x; r < M; r += gridDim.x) {
        float q = qkv[(long)r * 768 + j];
        float k = qkv[(long)r * 768 + 256 + j];
        aks += k;
        aq2 += q * q;
        ak2 += k * k;
    }
    atomicAdd(&red[j], aks);
    float q2 = block_sum_256(aq2, sm);
    float k2 = block_sum_256(ak2, sm);
    if (threadIdx.x == 0) {
        atomicAdd(&red[256], q2);
        atomicAdd(&red[257], k2);
    }
}

// ---------------- zero small accumulators ----------------
__global__ void zero_kernel(float* __restrict__ kvs, float* __restrict__ red)
{
    int i = blockIdx.x * blockDim.x + threadIdx.x;
    if (i < 256 * 256) kvs[i] = 0.f;
    if (i < 272) red[i] = 0.f;
}

// ---------------- LN + ReLU (input layer) ----------------
__global__ void __launch_bounds__(256) ln_relu_kernel(
    const float* __restrict__ in, float* __restrict__ out,
    const float* __restrict__ g, const float* __restrict__ b)
{
    __shared__ float sm[8];
    long row = blockIdx.x;
    int j = threadIdx.x;
    float x = in[row * 256 + j];
    float mu = block_sum_256(x, sm) * (1.f / 256.f);
    float d = x - mu;
    float var = block_sum_256(d * d, sm) * (1.f / 256.f);
    float y = g[j] * d * rsqrtf(var + 1e-5f) + b[j];
    out[row * 256 + j] = fmaxf(y, 0.f);
}

// ---------------- attention epilogue + residual + LN ----------------
__global__ void __launch_bounds__(256) attn_epilogue(
    const float* __restrict__ attn_raw,   // raw q @ (k^T v)
    const float* __restrict__ qkv,
    float* __restrict__ h,                // prev in, LN output out
    const float* __restrict__ red,
    const float* __restrict__ g, const float* __restrict__ b,
    float nNodes)
{
    __shared__ float sm[8];
    long row = blockIdx.x;
    int j = threadIdx.x;
    float ds = 1.f / (sqrtf(red[256]) * sqrtf(red[257]));   // 1/(||q|| * ||k||)
    float q = qkv[row * 768 + j];
    float s = block_sum_256(q * red[j], sm);                // raw q . ks_sum
    float norml = s * ds + nNodes;
    float v = qkv[row * 768 + 512 + j];
    float num = attn_raw[row * 256 + j] * ds + nNodes * v;
    float hv = 0.5f * (num / norml) + 0.5f * h[row * 256 + j];
    float mu = block_sum_256(hv, sm) * (1.f / 256.f);
    float d = hv - mu;
    float var = block_sum_256(d * d, sm) * (1.f / 256.f);
    h[row * 256 + j] = g[j] * d * rsqrtf(var + 1e-5f) + b[j];
}

// ---------------- concat Wq|Wk|Wv into one [256,768] matrix ----------------
__global__ void concat_w(const float* __restrict__ Wq, const float* __restrict__ Wk,
                         const float* __restrict__ Wv,
                         const float* __restrict__ bq, const float* __restrict__ bk,
                         const float* __restrict__ bv,
                         float* __restrict__ W, float* __restrict__ b)
{
    int idx = blockIdx.x * 256 + threadIdx.x;
    if (idx < 256 * 768) {
        int k = idx / 768, c = idx % 768;
        float v = (c < 256) ? Wq[k * 256 + c]
                : (c < 512) ? Wk[k * 256 + c - 256]
                            : Wv[k * 256 + c - 512];
        W[idx] = v;
    }
    if (idx < 768) {
        b[idx] = (idx < 256) ? bq[idx] : (idx < 512) ? bk[idx - 256] : bv[idx - 512];
    }
}

// ---------------- output GEMM: [M,256] @ [256,40] + bias ----------------
__global__ void __launch_bounds__(256) out_gemm(
    const float* __restrict__ h, const float* __restrict__ W,
    const float* __restrict__ bias, float* __restrict__ out, int M)
{
    __shared__ float hs[64][65];
    __shared__ float Ws[64][40];
    const int r0 = blockIdx.x * 64;
    const int tid = threadIdx.x;
    const int r = tid & 63, cg = tid >> 6;   // 4 col-groups of 10
    float acc[10];
    #pragma unroll
    for (int j = 0; j < 10; j++) acc[j] = 0.f;

    for (int k0 = 0; k0 < 256; k0 += 64) {
        #pragma unroll
        for (int s = 0; s < 4; s++) {
            int l = tid + s * 256;
            int hr = l >> 4;
            int hk = (l & 15) * 4;
            float4 hv = make_float4(0.f, 0.f, 0.f, 0.f);
            int gr = r0 + hr;
            if (gr < M) hv = *reinterpret_cast<const float4*>(&h[(long)gr * 256 + k0 + hk]);
            hs[hr][hk + 0] = hv.x; hs[hr][hk + 1] = hv.y;
            hs[hr][hk + 2] = hv.z; hs[hr][hk + 3] = hv.w;
        }
        #pragma unroll
        for (int s = 0; s < 10; s++) {
            int l = tid + s * 256;
            int wk = l / 40, wc = l % 40;
            Ws[wk][wc] = W[(k0 + wk) * 40 + wc];
        }
        __syncthreads();
        #pragma unroll
        for (int k = 0; k < 64; k++) {
            float a = hs[r][k];
            #pragma unroll
            for (int j = 0; j < 10; j++)
                acc[j] += a * Ws[k][cg * 10 + j];
        }
        __syncthreads();
    }
    int gr = r0 + r;
    if (gr < M) {
        #pragma unroll
        for (int j = 0; j < 10; j++)
            out[(long)gr * 40 + cg * 10 + j] = acc[j] + bias[cg * 10 + j];
    }
}

// ---------------- launch ----------------
extern "C" void kernel_launch(void* const* d_in, const int* in_sizes, int n_in,
                              void* d_out, int out_size)
{
    const float* x     = (const float*)d_in[0];
    // d_in[1] = edge_index (unused, use_graph=False)
    const float* W_in  = (const float*)d_in[2];
    const float* b_in  = (const float*)d_in[3];
    const float* ln0g  = (const float*)d_in[4];
    const float* ln0b  = (const float*)d_in[5];
    const float* Wq[2] = {(const float*)d_in[6],  (const float*)d_in[14]};
    const float* bq[2] = {(const float*)d_in[7],  (const float*)d_in[15]};
    const float* Wk[2] = {(const float*)d_in[8],  (const float*)d_in[16]};
    const float* bk[2] = {(const float*)d_in[9],  (const float*)d_in[17]};
    const float* Wv[2] = {(const float*)d_in[10], (const float*)d_in[18]};
    const float* bv[2] = {(const float*)d_in[11], (const float*)d_in[19]};
    const float* lng[2] = {(const float*)d_in[12], (const float*)d_in[20]};
    const float* lnb[2] = {(const float*)d_in[13], (const float*)d_in[21]};
    const float* W_out = (const float*)d_in[22];
    const float* b_out = (const float*)d_in[23];
    float* out = (float*)d_out;

    const int M = in_sizes[0] / 512;

    float *ph, *pqkv, *pattn, *pkvs, *pred, *pW, *pb;
    cudaGetSymbolAddress((void**)&ph,    g_h);
    cudaGetSymbolAddress((void**)&pqkv,  g_qkv);
    cudaGetSymbolAddress((void**)&pattn, g_attn);
    cudaGetSymbolAddress((void**)&pkvs,  g_kvs);
    cudaGetSymbolAddress((void**)&pred,  g_red);
    cudaGetSymbolAddress((void**)&pW,    g_W);
    cudaGetSymbolAddress((void**)&pb,    g_b);

    const int gy = (M + 127) / 128;
    dim3 blk(256);

    // h = relu(LN(x @ W_in + b_in))
    sgemm_k<<<dim3(2, gy), blk>>>(x, 512, W_in, 256, b_in, pattn, 256, M, 512);
    ln_relu_kernel<<<M, 256>>>(pattn, ph, ln0g, ln0b);

    for (int l = 0; l < 2; l++) {
        concat_w<<<768, 256>>>(Wq[l], Wk[l], Wv[l], bq[l], bk[l], bv[l], pW, pb);
        zero_kernel<<<256, 256>>>(pkvs, pred);
        // qkv = h @ [Wq|Wk|Wv] + bias
        sgemm_k<<<dim3(6, gy), blk>>>(ph, 256, pW, 768, pb, pqkv, 768, M, 256);
        // ks_sum, ||q||^2, ||k||^2
        reduce_qk<<<512, 256>>>(pqkv, pred, M);
        // kvs = k^T v (raw)
        kvs_kernel<<<dim3(16, (M + 1023) / 1024), blk>>>(pqkv, pkvs, M, 1024);
        // attn_raw = q @ kvs (raw)
        sgemm_k<<<dim3(2, gy), blk>>>(pqkv, 768, pkvs, 256, nullptr, pattn, 256, M, 256);
        // h = LN(0.5 * attn + 0.5 * h)
        attn_epilogue<<<M, 256>>>(pattn, pqkv, ph, pred, lng[l], lnb[l], (float)M);
    }

    // out = h @ W_out + b_out
    out_gemm<<<(M + 63) / 64, 256>>>(ph, W_out, b_out, out, M);
}